// round 6
// baseline (speedup 1.0000x reference)
#include <cuda_runtime.h>
#include <cstdint>

// TDLoss: GAE backward scan over time + squared TD loss.
// Shapes: [T, B] time-major, T=256, B=65536.
// Inputs: reward f32, step_type i32, discount f32, value f32, target_value f32.
// Output: loss f32 [T, B], with loss[T-1, :] = 0.
//
// R6 (= R5 resubmit; infra ate R5): cp.async (LDGSTS) staging pipeline,
// depth 8. Decouples memory-level parallelism from the register file: each
// thread keeps 8 stages x 5 x 8B = 320B in flight via async copies into
// smem, consumes only its own slots (no block barriers), registers hold
// only the compute state.

namespace {
constexpr int   T_STEPS = 256;
constexpr int   B_COLS  = 65536;
constexpr int   W2      = B_COLS / 2;          // float2 columns = 32768
constexpr int   NTHR    = 64;
constexpr int   NBLK    = W2 / NTHR;           // 512
constexpr int   D       = 8;                   // pipeline depth (power of 2)
constexpr float GAMMA   = 0.99f;
constexpr float LAMBDA  = 0.95f;
constexpr int   STEP_TYPE_LAST = 2;
}

__device__ __forceinline__ void cp_async8(uint32_t smem_dst, const void* gmem_src) {
    asm volatile("cp.async.ca.shared.global [%0], [%1], 8;\n"
                 :: "r"(smem_dst), "l"(gmem_src));
}
__device__ __forceinline__ void cp_commit() {
    asm volatile("cp.async.commit_group;\n" ::: "memory");
}
template <int N>
__device__ __forceinline__ void cp_wait() {
    asm volatile("cp.async.wait_group %0;\n" :: "n"(N) : "memory");
}

__global__ void __launch_bounds__(NTHR)
td_loss_kernel(const float2* __restrict__ reward,
               const int2*   __restrict__ step_type,
               const float2* __restrict__ discount,
               const float2* __restrict__ value,
               const float2* __restrict__ tv,
               float2*       __restrict__ out)
{
    __shared__ float2 s_r [D][NTHR];
    __shared__ float2 s_d [D][NTHR];
    __shared__ float2 s_tv[D][NTHR];
    __shared__ int2   s_st[D][NTHR];
    __shared__ float2 s_v [D][NTHR];

    const int tid = threadIdx.x;
    const int c   = blockIdx.x * NTHR + tid;    // this thread's float2 column

    const uint32_t a_r  = (uint32_t)__cvta_generic_to_shared(&s_r [0][tid]);
    const uint32_t a_d  = (uint32_t)__cvta_generic_to_shared(&s_d [0][tid]);
    const uint32_t a_tv = (uint32_t)__cvta_generic_to_shared(&s_tv[0][tid]);
    const uint32_t a_st = (uint32_t)__cvta_generic_to_shared(&s_st[0][tid]);
    const uint32_t a_v  = (uint32_t)__cvta_generic_to_shared(&s_v [0][tid]);
    constexpr uint32_t STRIDE = NTHR * 8;       // bytes per stage per array

    // Stage issue: fetch inputs needed for scan step t into buffer `buf`.
    auto issue = [&](int t, int buf) {
        const int i1 = (t + 1) * W2 + c;
        const int i0 = t * W2 + c;
        const uint32_t off = (uint32_t)buf * STRIDE;
        cp_async8(a_r  + off, reward    + i1);
        cp_async8(a_d  + off, discount  + i1);
        cp_async8(a_tv + off, tv        + i0);
        cp_async8(a_st + off, step_type + i0);
        cp_async8(a_v  + off, value     + i0);
        cp_commit();
    };

    // Zero the last time row (output is poisoned by the harness).
    out[(T_STEPS - 1) * W2 + c] = make_float2(0.f, 0.f);

    // Prologue: fill the pipeline for t = 254 .. 254-(D-1).
    #pragma unroll
    for (int i = 0; i < D; ++i)
        issue(T_STEPS - 2 - i, i);

    float2 adv = make_float2(0.f, 0.f);
    float2 tvn = tv[(T_STEPS - 1) * W2 + c];    // target_value[t+1] carry

    #pragma unroll 4
    for (int k = 0; k < T_STEPS - 1; ++k) {
        const int t   = T_STEPS - 2 - k;
        const int buf = k & (D - 1);

        // Wait until at most D-1 groups pending -> oldest (this buf) landed.
        cp_wait<D - 1>();

        const float2 r   = s_r [buf][tid];
        const float2 d   = s_d [buf][tid];
        const float2 tvc = s_tv[buf][tid];
        const int2   st  = s_st[buf][tid];
        const float2 v   = s_v [buf][tid];

        float2 o;
        #define LANE(X)                                                     \
        {                                                                   \
            const float disc  = d.X * GAMMA;                                \
            const float delta = fmaf(disc, tvn.X, r.X) - tvc.X;             \
            const float wd    = disc * LAMBDA;                              \
            float a           = fmaf(wd, adv.X, delta);                     \
            a                 = (st.X == STEP_TYPE_LAST) ? 0.f : a;         \
            adv.X             = a;                                          \
            const float diff  = v.X - (a + tvc.X);                          \
            o.X               = diff * diff;                                \
        }
        LANE(x) LANE(y)
        #undef LANE

        out[t * W2 + c] = o;
        tvn = tvc;

        // Refill this buffer with stage t-D (if any). Safe: this thread is
        // the only reader of its slots and has consumed them above.
        const int tn = t - D;
        if (tn >= 0)
            issue(tn, buf);
        else
            cp_commit();   // keep group count in step so wait<D-1> stays aligned
    }
}

extern "C" void kernel_launch(void* const* d_in, const int* in_sizes, int n_in,
                              void* d_out, int out_size)
{
    const float2* reward    = (const float2*)d_in[0];
    const int2*   step_type = (const int2*)  d_in[1];
    const float2* discount  = (const float2*)d_in[2];
    const float2* value     = (const float2*)d_in[3];
    const float2* tv        = (const float2*)d_in[4];
    float2*       out       = (float2*)d_out;

    td_loss_kernel<<<NBLK, NTHR>>>(reward, step_type, discount, value, tv, out);
}